// round 2
// baseline (speedup 1.0000x reference)
#include <cuda_runtime.h>

#define NB 16
#define CD 256
#define HW 4096
#define KA 512
#define ROWS (NB*HW)   // 65536

// Scratch (allocation-free rule: __device__ globals)
__device__ float g_A0[(size_t)ROWS * KA];   // 128 MB: exp(scores/T)
__device__ float g_S[NB * CD * KA];         // 8 MB: gathered, L2-normalized anchors
__device__ float g_invnorm[ROWS];           // per (n,hw) inverse channel norm
__device__ float g_colsum[KA];              // Sinkhorn column-sum accumulator
__device__ float g_cvec[KA];                // Sinkhorn column scaling c

__global__ void zero_colsum_kernel() { g_colsum[threadIdx.x] = 0.0f; }

// ---------------------------------------------------------------- norms
__global__ void norm_kernel(const float* __restrict__ x) {
    int i = blockIdx.x * blockDim.x + threadIdx.x;   // n*HW + hw
    int n = i >> 12;
    int hw = i & 4095;
    const float* p = x + (size_t)n * CD * HW + hw;
    float acc = 0.0f;
#pragma unroll 16
    for (int c = 0; c < CD; ++c) {
        float v = p[(size_t)c * HW];
        acc = fmaf(v, v, acc);
    }
    g_invnorm[i] = 1.0f / fmaxf(sqrtf(acc), 1e-12f);
}

// ---------------------------------------------------------------- anchor gather
__global__ void gather_kernel(const float* __restrict__ x, const int* __restrict__ idx) {
    int t = blockIdx.x * blockDim.x + threadIdx.x;   // n*CD*KA + c*KA + j
    int j  = t & (KA - 1);
    int nc = t >> 9;          // n*CD + c
    int n  = nc >> 8;
    int pos = idx[j];
    g_S[t] = x[(size_t)nc * HW + pos] * g_invnorm[n * HW + pos];
}

// ---------------------------------------------------------------- score GEMM + exp + colsum
// A0[i=n*HW+hw][j] = exp( invnorm[i] * sum_c x[n,c,hw]*S[n,c,j] / T )
// Tiles: BM=128 (hw), BN=128 (j), BK=16 (c); 256 threads, 8x8 microtile.
__global__ __launch_bounds__(256) void score_gemm(const float* __restrict__ x) {
    int n   = blockIdx.z;
    int hw0 = blockIdx.x * 128;
    int j0  = blockIdx.y * 128;
    __shared__ float Xs[16][128];
    __shared__ float Ss[16][128];
    __shared__ float colred[128];
    int tid = threadIdx.x;
    int ty = tid >> 4, tx = tid & 15;
    float acc[8][8];
#pragma unroll
    for (int mi = 0; mi < 8; ++mi)
#pragma unroll
        for (int mj = 0; mj < 8; ++mj) acc[mi][mj] = 0.0f;

    const float* Xbase = x   + (size_t)n * CD * HW + hw0;
    const float* Sbase = g_S + (size_t)n * CD * KA + j0;

    for (int k0 = 0; k0 < CD; k0 += 16) {
#pragma unroll
        for (int it = 0; it < 2; ++it) {
            int idx = tid + 256 * it;     // 0..511 float4 slots
            int row = idx >> 5;           // 0..15 (c)
            int q4  = idx & 31;           // float4 within 128 floats
            float4 v = *(const float4*)(Xbase + (size_t)(k0 + row) * HW + q4 * 4);
            *(float4*)(&Xs[row][q4 * 4]) = v;
            float4 w = *(const float4*)(Sbase + (size_t)(k0 + row) * KA + q4 * 4);
            *(float4*)(&Ss[row][q4 * 4]) = w;
        }
        __syncthreads();
#pragma unroll
        for (int kk = 0; kk < 16; ++kk) {
            float a[8], b[8];
            *(float4*)(a)     = *(float4*)(&Xs[kk][ty * 8]);
            *(float4*)(a + 4) = *(float4*)(&Xs[kk][ty * 8 + 4]);
            *(float4*)(b)     = *(float4*)(&Ss[kk][tx * 8]);
            *(float4*)(b + 4) = *(float4*)(&Ss[kk][tx * 8 + 4]);
#pragma unroll
            for (int mi = 0; mi < 8; ++mi)
#pragma unroll
                for (int mj = 0; mj < 8; ++mj)
                    acc[mi][mj] = fmaf(a[mi], b[mj], acc[mi][mj]);
        }
        __syncthreads();
    }

    // epilogue: exp(score/T), store A0, accumulate column sums (first Sinkhorn colsum)
    if (tid < 128) colred[tid] = 0.0f;
    __syncthreads();
    float colp[8];
#pragma unroll
    for (int mj = 0; mj < 8; ++mj) colp[mj] = 0.0f;
#pragma unroll
    for (int mi = 0; mi < 8; ++mi) {
        int hw = hw0 + ty * 8 + mi;
        int i  = n * HW + hw;
        float sc = g_invnorm[i] * (1.0f / 0.3f);
        float vals[8];
#pragma unroll
        for (int mj = 0; mj < 8; ++mj) {
            float v = __expf(acc[mi][mj] * sc);
            vals[mj] = v;
            colp[mj] += v;
        }
        float* dst = g_A0 + (size_t)i * KA + j0 + tx * 8;
        *(float4*)(dst)     = make_float4(vals[0], vals[1], vals[2], vals[3]);
        *(float4*)(dst + 4) = make_float4(vals[4], vals[5], vals[6], vals[7]);
    }
#pragma unroll
    for (int mj = 0; mj < 8; ++mj) atomicAdd(&colred[tx * 8 + mj], colp[mj]);
    __syncthreads();
    if (tid < 128) atomicAdd(&g_colsum[j0 + tid], colred[tid]);
}

// ---------------------------------------------------------------- c = 1/colsum; reset
__global__ void recip_kernel() {
    int j = threadIdx.x;
    g_cvec[j] = 1.0f / fmaxf(g_colsum[j], 1e-30f);
    g_colsum[j] = 0.0f;
}

// ---------------------------------------------------------------- fused Sinkhorn pass
// For each row i: r_i = 1/(A0_i . c); accumulate colsum_j += r_i * A0_ij.
// 1 warp per row, 16 rows per warp, 128 rows per block.
__global__ __launch_bounds__(256) void sk_pass() {
    __shared__ float cred[KA];
    int tid = threadIdx.x;
    cred[tid] = 0.0f; cred[tid + 256] = 0.0f;
    __syncthreads();
    int warp = tid >> 5, lane = tid & 31;
    float4 c4[4];
#pragma unroll
    for (int m = 0; m < 4; ++m) c4[m] = ((const float4*)g_cvec)[m * 32 + lane];
    float4 ca[4];
#pragma unroll
    for (int m = 0; m < 4; ++m) ca[m] = make_float4(0.f, 0.f, 0.f, 0.f);

    size_t rbase = (size_t)blockIdx.x * 128 + warp * 16;
    for (int t = 0; t < 16; ++t) {
        const float4* row = (const float4*)(g_A0 + (rbase + t) * KA);
        float4 a[4];
        float d = 0.0f;
#pragma unroll
        for (int m = 0; m < 4; ++m) {
            a[m] = row[m * 32 + lane];
            d += a[m].x * c4[m].x + a[m].y * c4[m].y + a[m].z * c4[m].z + a[m].w * c4[m].w;
        }
#pragma unroll
        for (int s = 16; s > 0; s >>= 1) d += __shfl_xor_sync(0xffffffffu, d, s);
        float r = 1.0f / fmaxf(d, 1e-30f);
#pragma unroll
        for (int m = 0; m < 4; ++m) {
            ca[m].x = fmaf(r, a[m].x, ca[m].x);
            ca[m].y = fmaf(r, a[m].y, ca[m].y);
            ca[m].z = fmaf(r, a[m].z, ca[m].z);
            ca[m].w = fmaf(r, a[m].w, ca[m].w);
        }
    }
#pragma unroll
    for (int m = 0; m < 4; ++m) {
        int base = (m * 32 + lane) * 4;
        atomicAdd(&cred[base + 0], ca[m].x);
        atomicAdd(&cred[base + 1], ca[m].y);
        atomicAdd(&cred[base + 2], ca[m].z);
        atomicAdd(&cred[base + 3], ca[m].w);
    }
    __syncthreads();
    atomicAdd(&g_colsum[tid],       cred[tid]);
    atomicAdd(&g_colsum[tid + 256], cred[tid + 256]);
}

// ---------------------------------------------------------------- reconstruct GEMM
// out[n,c,hw] = r_i * sum_j (A0[i,j]*c_j) * S[n,c,j],  r_i = 1/sum_j A0[i,j]*c_j
// Tiles: BM=128 (c), BN=128 (hw), BK=16 (j); rowdot d_i fused into the k-loop.
__global__ __launch_bounds__(256) void recon_gemm(float* __restrict__ out) {
    int n   = blockIdx.z;
    int hw0 = blockIdx.x * 128;
    int c0  = blockIdx.y * 128;
    __shared__ float Ds[16][128];   // S^T tile [j][c]
    __shared__ float Bs[16][128];   // (A0*c)^T tile [j][hw]
    __shared__ float dsum[128];
    int tid = threadIdx.x;
    int ty = tid >> 4, tx = tid & 15;
    float acc[8][8];
#pragma unroll
    for (int mi = 0; mi < 8; ++mi)
#pragma unroll
        for (int mj = 0; mj < 8; ++mj) acc[mi][mj] = 0.0f;
    float dpart = 0.0f;

    const float* Sbase = g_S  + (size_t)n * CD * KA;
    const float* Abase = g_A0 + (size_t)n * HW * KA;

    for (int k0 = 0; k0 < KA; k0 += 16) {
#pragma unroll
        for (int it = 0; it < 2; ++it) {
            int idx = tid + 256 * it;   // 0..511
            int row = idx >> 2;         // 0..127
            int q4  = idx & 3;          // j-float4 within BK
            float4 v = *(const float4*)(Sbase + (size_t)(c0 + row) * KA + k0 + q4 * 4);
            Ds[q4 * 4 + 0][row] = v.x; Ds[q4 * 4 + 1][row] = v.y;
            Ds[q4 * 4 + 2][row] = v.z; Ds[q4 * 4 + 3][row] = v.w;
            float4 cc = *(const float4*)(g_cvec + k0 + q4 * 4);
            float4 w = *(const float4*)(Abase + (size_t)(hw0 + row) * KA + k0 + q4 * 4);
            w.x *= cc.x; w.y *= cc.y; w.z *= cc.z; w.w *= cc.w;
            Bs[q4 * 4 + 0][row] = w.x; Bs[q4 * 4 + 1][row] = w.y;
            Bs[q4 * 4 + 2][row] = w.z; Bs[q4 * 4 + 3][row] = w.w;
        }
        __syncthreads();
        if (tid < 128) {
#pragma unroll
            for (int kk = 0; kk < 16; ++kk) dpart += Bs[kk][tid];
        }
#pragma unroll
        for (int kk = 0; kk < 16; ++kk) {
            float a[8], b[8];
            *(float4*)(a)     = *(float4*)(&Ds[kk][ty * 8]);
            *(float4*)(a + 4) = *(float4*)(&Ds[kk][ty * 8 + 4]);
            *(float4*)(b)     = *(float4*)(&Bs[kk][tx * 8]);
            *(float4*)(b + 4) = *(float4*)(&Bs[kk][tx * 8 + 4]);
#pragma unroll
            for (int mi = 0; mi < 8; ++mi)
#pragma unroll
                for (int mj = 0; mj < 8; ++mj)
                    acc[mi][mj] = fmaf(a[mi], b[mj], acc[mi][mj]);
        }
        __syncthreads();
    }
    if (tid < 128) dsum[tid] = dpart;
    __syncthreads();
    float rin[8];
#pragma unroll
    for (int mj = 0; mj < 8; ++mj) rin[mj] = 1.0f / fmaxf(dsum[tx * 8 + mj], 1e-30f);
#pragma unroll
    for (int mi = 0; mi < 8; ++mi) {
        float* dst = out + (size_t)(n * CD + c0 + ty * 8 + mi) * HW + hw0 + tx * 8;
        *(float4*)(dst)     = make_float4(acc[mi][0] * rin[0], acc[mi][1] * rin[1],
                                          acc[mi][2] * rin[2], acc[mi][3] * rin[3]);
        *(float4*)(dst + 4) = make_float4(acc[mi][4] * rin[4], acc[mi][5] * rin[5],
                                          acc[mi][6] * rin[6], acc[mi][7] * rin[7]);
    }
}

// ----------------------------------------------------------------
extern "C" void kernel_launch(void* const* d_in, const int* in_sizes, int n_in,
                              void* d_out, int out_size) {
    const float* x  = (const float*)d_in[0];
    const int* idx  = (const int*)d_in[1];
    float* out = (float*)d_out;

    zero_colsum_kernel<<<1, KA>>>();
    norm_kernel<<<ROWS / 256, 256>>>(x);
    gather_kernel<<<(NB * CD * KA) / 256, 256>>>(x, idx);
    // score GEMM (writes A0, accumulates colsum for c1)
    score_gemm<<<dim3(HW / 128, KA / 128, NB), 256>>>(x);
    recip_kernel<<<1, KA>>>();   // c1
    // 3 fused Sinkhorn passes -> c2, c3, c4
    for (int it = 0; it < 3; ++it) {
        sk_pass<<<ROWS / 128, 256>>>();
        recip_kernel<<<1, KA>>>();
    }
    // reconstruct (computes r4 on the fly via fused rowdot)
    recon_gemm<<<dim3(HW / 128, CD / 128, NB), 256>>>(out);
}

// round 4
// speedup vs baseline: 1.6295x; 1.6295x over previous
#include <cuda_runtime.h>
#include <cuda_bf16.h>
#include <cstdint>

#define NB 16
#define CD 256
#define HW 4096
#define KA 512
#define ROWS (NB*HW)   // 65536

// ---------------- scratch (__device__ globals; no allocations) ----------------
__device__ __align__(16) float g_A0[(size_t)ROWS * KA];              // 128 MB
__device__ __align__(16) __nv_bfloat16 g_Xh[(size_t)ROWS * CD];      // X^T hi [n][hw][c] 32MB
__device__ __align__(16) __nv_bfloat16 g_Xl[(size_t)ROWS * CD];      // X^T lo
__device__ __align__(16) __nv_bfloat16 g_Shj[(size_t)NB*KA*CD];      // S hi [n][j][c]
__device__ __align__(16) __nv_bfloat16 g_Slj[(size_t)NB*KA*CD];      // S lo [n][j][c]
__device__ __align__(16) __nv_bfloat16 g_Shc[(size_t)NB*CD*KA];      // S hi [n][c][j]
__device__ __align__(16) __nv_bfloat16 g_Slc[(size_t)NB*CD*KA];      // S lo [n][c][j]
__device__ float g_invnorm[ROWS];
__device__ float g_colsum[KA];
__device__ float g_cvec[KA];

// ---------------- helpers ----------------
__device__ __forceinline__ uint32_t smem_u32(const void* p) {
    uint32_t a;
    asm("{ .reg .u64 t; cvta.to.shared.u64 t, %1; cvt.u32.u64 %0, t; }" : "=r"(a) : "l"(p));
    return a;
}
__device__ __forceinline__ uint32_t swz(uint32_t o) { return o ^ ((o >> 3) & 0x70); }
__device__ __forceinline__ uint32_t pack_bf2(__nv_bfloat16 a, __nv_bfloat16 b) {
    return (uint32_t)__bfloat16_as_ushort(a) | ((uint32_t)__bfloat16_as_ushort(b) << 16);
}
__device__ __forceinline__ void split_bf(float f, __nv_bfloat16& h, __nv_bfloat16& l) {
    h = __float2bfloat16(f);
    l = __float2bfloat16(f - __bfloat162float(h));
}
__device__ __forceinline__ void ldm4(uint32_t addr, uint32_t r[4]) {
    asm volatile("ldmatrix.sync.aligned.m8n8.x4.shared.b16 {%0,%1,%2,%3}, [%4];"
        : "=r"(r[0]), "=r"(r[1]), "=r"(r[2]), "=r"(r[3]) : "r"(addr));
}
__device__ __forceinline__ void mma16816(float c[4], const uint32_t a[4],
                                         uint32_t b0, uint32_t b1) {
    asm volatile("mma.sync.aligned.m16n8k16.row.col.f32.bf16.bf16.f32 "
        "{%0,%1,%2,%3}, {%4,%5,%6,%7}, {%8,%9}, {%0,%1,%2,%3};"
        : "+f"(c[0]), "+f"(c[1]), "+f"(c[2]), "+f"(c[3])
        : "r"(a[0]), "r"(a[1]), "r"(a[2]), "r"(a[3]), "r"(b0), "r"(b1));
}
// A-fragment (m16 x k16) ldmatrix address: rows = m, k-contiguous 128B SW128 rows
__device__ __forceinline__ uint32_t afrag_addr(uint32_t base, int mbase, int s, int lane) {
    int row = mbase + (lane & 7) + ((lane >> 3) & 1) * 8;
    int unit = 2 * s + (lane >> 4);
    return base + swz((uint32_t)(row * 128 + unit * 16));
}
// B-fragment (n16 x k16): rows = n, k-contiguous
__device__ __forceinline__ uint32_t bfrag_addr(uint32_t base, int nbase, int s, int lane) {
    int row = nbase + (lane & 7) + ((lane >> 4) & 1) * 8;
    int unit = 2 * s + ((lane >> 3) & 1);
    return base + swz((uint32_t)(row * 128 + unit * 16));
}

// SMEM layout (dynamic): dsum/cvec + 4 x 16KB tiles
#define OFF_DS   0          // 128 floats (recon dsum)
#define OFF_CV   512        // 512 floats (recon cvec copy)
#define OFF_AH   4096
#define OFF_AL   (4096 + 16384)
#define OFF_BH   (4096 + 32768)
#define OFF_BL   (4096 + 49152)
#define TC_SMEM  (4096 + 65536)   // 69632

// ---------------- small kernels ----------------
__global__ void zero_colsum_kernel() { g_colsum[threadIdx.x] = 0.0f; }

__global__ void norm_kernel(const float* __restrict__ x) {
    int i = blockIdx.x * blockDim.x + threadIdx.x;
    int n = i >> 12, hw = i & 4095;
    const float* p = x + (size_t)n * CD * HW + hw;
    float acc = 0.0f;
#pragma unroll 16
    for (int c = 0; c < CD; ++c) { float v = p[(size_t)c * HW]; acc = fmaf(v, v, acc); }
    g_invnorm[i] = 1.0f / fmaxf(sqrtf(acc), 1e-12f);
}

// transpose x[n][c][hw] -> Xh/Xl [n][hw][c] (bf16 hi/lo)
__global__ void xt_kernel(const float* __restrict__ x) {
    __shared__ float t[32][33];
    int n = blockIdx.z, hw0 = blockIdx.x * 32, c0 = blockIdx.y * 32;
    int tx = threadIdx.x, ty = threadIdx.y;   // 32 x 8
#pragma unroll
    for (int r = 0; r < 32; r += 8)
        t[ty + r][tx] = x[((size_t)n * CD + c0 + ty + r) * HW + hw0 + tx];
    __syncthreads();
#pragma unroll
    for (int r = 0; r < 32; r += 8) {
        float v = t[tx][ty + r];
        size_t o = ((size_t)n * HW + hw0 + ty + r) * CD + c0 + tx;
        __nv_bfloat16 h, l; split_bf(v, h, l);
        g_Xh[o] = h; g_Xl[o] = l;
    }
}

__global__ void gather_cj(const float* __restrict__ x, const int* __restrict__ idx) {
    int t = blockIdx.x * blockDim.x + threadIdx.x;   // [n][c][j], j fastest
    int j = t & (KA - 1);
    int nc = t >> 9;
    int n = nc >> 8;
    int pos = idx[j];
    float v = x[(size_t)nc * HW + pos] * g_invnorm[n * HW + pos];
    __nv_bfloat16 h, l; split_bf(v, h, l);
    g_Shc[t] = h; g_Slc[t] = l;
}
__global__ void gather_jc(const float* __restrict__ x, const int* __restrict__ idx) {
    int t = blockIdx.x * blockDim.x + threadIdx.x;   // [n][j][c], c fastest
    int c = t & (CD - 1);
    int nj = t >> 8;
    int j = nj & (KA - 1);
    int n = nj >> 9;
    int pos = idx[j];
    float v = x[((size_t)n * CD + c) * HW + pos] * g_invnorm[n * HW + pos];
    __nv_bfloat16 h, l; split_bf(v, h, l);
    g_Shj[t] = h; g_Slj[t] = l;
}

__global__ void recip_kernel() {
    int j = threadIdx.x;
    g_cvec[j] = 1.0f / fmaxf(g_colsum[j], 1e-30f);
    g_colsum[j] = 0.0f;
}

__global__ __launch_bounds__(256) void colsum0_kernel() {
    __shared__ float cred[KA];
    int tid = threadIdx.x;
    cred[tid] = 0.0f; cred[tid + 256] = 0.0f;
    __syncthreads();
    int warp = tid >> 5, lane = tid & 31;
    float4 ca[4];
#pragma unroll
    for (int m = 0; m < 4; ++m) ca[m] = make_float4(0.f, 0.f, 0.f, 0.f);
    size_t rbase = (size_t)blockIdx.x * 128 + warp * 16;
    for (int t = 0; t < 16; ++t) {
        const float4* row = (const float4*)(g_A0 + (rbase + t) * KA);
#pragma unroll
        for (int m = 0; m < 4; ++m) {
            float4 a = row[m * 32 + lane];
            ca[m].x += a.x; ca[m].y += a.y; ca[m].z += a.z; ca[m].w += a.w;
        }
    }
#pragma unroll
    for (int m = 0; m < 4; ++m) {
        int base = (m * 32 + lane) * 4;
        atomicAdd(&cred[base + 0], ca[m].x); atomicAdd(&cred[base + 1], ca[m].y);
        atomicAdd(&cred[base + 2], ca[m].z); atomicAdd(&cred[base + 3], ca[m].w);
    }
    __syncthreads();
    atomicAdd(&g_colsum[tid], cred[tid]);
    atomicAdd(&g_colsum[tid + 256], cred[tid + 256]);
}

__global__ __launch_bounds__(256) void sk_pass() {
    __shared__ float cred[KA];
    int tid = threadIdx.x;
    cred[tid] = 0.0f; cred[tid + 256] = 0.0f;
    __syncthreads();
    int warp = tid >> 5, lane = tid & 31;
    float4 c4[4];
#pragma unroll
    for (int m = 0; m < 4; ++m) c4[m] = ((const float4*)g_cvec)[m * 32 + lane];
    float4 ca[4];
#pragma unroll
    for (int m = 0; m < 4; ++m) ca[m] = make_float4(0.f, 0.f, 0.f, 0.f);
    size_t rbase = (size_t)blockIdx.x * 128 + warp * 16;
    for (int t = 0; t < 16; ++t) {
        const float4* row = (const float4*)(g_A0 + (rbase + t) * KA);
        float4 a[4]; float d = 0.0f;
#pragma unroll
        for (int m = 0; m < 4; ++m) {
            a[m] = row[m * 32 + lane];
            d += a[m].x * c4[m].x + a[m].y * c4[m].y + a[m].z * c4[m].z + a[m].w * c4[m].w;
        }
#pragma unroll
        for (int s = 16; s > 0; s >>= 1) d += __shfl_xor_sync(0xffffffffu, d, s);
        float r = 1.0f / fmaxf(d, 1e-30f);
#pragma unroll
        for (int m = 0; m < 4; ++m) {
            ca[m].x = fmaf(r, a[m].x, ca[m].x); ca[m].y = fmaf(r, a[m].y, ca[m].y);
            ca[m].z = fmaf(r, a[m].z, ca[m].z); ca[m].w = fmaf(r, a[m].w, ca[m].w);
        }
    }
#pragma unroll
    for (int m = 0; m < 4; ++m) {
        int base = (m * 32 + lane) * 4;
        atomicAdd(&cred[base + 0], ca[m].x); atomicAdd(&cred[base + 1], ca[m].y);
        atomicAdd(&cred[base + 2], ca[m].z); atomicAdd(&cred[base + 3], ca[m].w);
    }
    __syncthreads();
    atomicAdd(&g_colsum[tid], cred[tid]);
    atomicAdd(&g_colsum[tid + 256], cred[tid + 256]);
}

// ================= score GEMM (mma.sync bf16 hi/lo) =================
// A0[n*HW+hw0+m][j0+nn] = exp(invnorm_i/T * sum_c Xt[m][c]*S[nn][c])
// CTA tile M=128(hw) N=128(j) K=256(c), BK=64, 8 warps of 32x64.
__global__ __launch_bounds__(256, 2) void score_mma() {
    extern __shared__ char smem[];
    uint32_t sb = smem_u32(smem);
    int tid = threadIdx.x, lane = tid & 31, w = tid >> 5;
    int n = blockIdx.z, hw0 = blockIdx.x * 128, j0 = blockIdx.y * 128;
    int wm = (w & 3) * 32, wn = (w >> 2) * 64;

    float acc[2][8][4];
#pragma unroll
    for (int a = 0; a < 2; ++a)
#pragma unroll
        for (int b = 0; b < 8; ++b)
#pragma unroll
            for (int c = 0; c < 4; ++c) acc[a][b][c] = 0.0f;

    int crow = tid >> 1, chalf = tid & 1;
    const uint4* aH = (const uint4*)(g_Xh + ((size_t)n * HW + hw0 + crow) * CD);
    const uint4* aL = (const uint4*)(g_Xl + ((size_t)n * HW + hw0 + crow) * CD);
    const uint4* bH = (const uint4*)(g_Shj + ((size_t)n * KA + j0 + crow) * CD);
    const uint4* bL = (const uint4*)(g_Slj + ((size_t)n * KA + j0 + crow) * CD);

    for (int ch = 0; ch < 4; ++ch) {
        // stage tiles (BK=64 -> 8 uint4 per 128B row, this thread does 4)
#pragma unroll
        for (int q = 0; q < 4; ++q) {
            int unit = chalf * 4 + q;
            uint32_t off = swz((uint32_t)(crow * 128 + unit * 16));
            int gi = ch * 8 + unit;
            *(uint4*)(smem + OFF_AH + off) = aH[gi];
            *(uint4*)(smem + OFF_AL + off) = aL[gi];
            *(uint4*)(smem + OFF_BH + off) = bH[gi];
            *(uint4*)(smem + OFF_BL + off) = bL[gi];
        }
        __syncthreads();
#pragma unroll
        for (int s = 0; s < 4; ++s) {
            uint32_t ah[2][4], al[2][4];
#pragma unroll
            for (int mt = 0; mt < 2; ++mt) {
                ldm4(afrag_addr(sb + OFF_AH, wm + mt * 16, s, lane), ah[mt]);
                ldm4(afrag_addr(sb + OFF_AL, wm + mt * 16, s, lane), al[mt]);
            }
#pragma unroll
            for (int ng = 0; ng < 4; ++ng) {
                uint32_t bh[4], bl[4];
                ldm4(bfrag_addr(sb + OFF_BH, wn + ng * 16, s, lane), bh);
                ldm4(bfrag_addr(sb + OFF_BL, wn + ng * 16, s, lane), bl);
#pragma unroll
                for (int mt = 0; mt < 2; ++mt) {
                    mma16816(acc[mt][2*ng],   ah[mt], bh[0], bh[1]);
                    mma16816(acc[mt][2*ng],   ah[mt], bl[0], bl[1]);
                    mma16816(acc[mt][2*ng],   al[mt], bh[0], bh[1]);
                    mma16816(acc[mt][2*ng+1], ah[mt], bh[2], bh[3]);
                    mma16816(acc[mt][2*ng+1], ah[mt], bl[2], bl[3]);
                    mma16816(acc[mt][2*ng+1], al[mt], bh[2], bh[3]);
                }
            }
        }
        __syncthreads();
    }

    // epilogue: exp(score * invnorm / T)
#pragma unroll
    for (int mt = 0; mt < 2; ++mt) {
        int i0 = n * HW + hw0 + wm + mt * 16 + (lane >> 2);
        int i1 = i0 + 8;
        float s0 = g_invnorm[i0] * (1.0f / 0.3f);
        float s1 = g_invnorm[i1] * (1.0f / 0.3f);
        float* r0 = g_A0 + (size_t)i0 * KA + j0 + wn + (lane & 3) * 2;
        float* r1 = g_A0 + (size_t)i1 * KA + j0 + wn + (lane & 3) * 2;
#pragma unroll
        for (int nt = 0; nt < 8; ++nt) {
            float2 v0 = make_float2(__expf(acc[mt][nt][0] * s0), __expf(acc[mt][nt][1] * s0));
            float2 v1 = make_float2(__expf(acc[mt][nt][2] * s1), __expf(acc[mt][nt][3] * s1));
            *(float2*)(r0 + nt * 8) = v0;
            *(float2*)(r1 + nt * 8) = v1;
        }
    }
}

// ================= reconstruct GEMM (mma.sync bf16 hi/lo) =================
// out[n][c0+m][hw0+nn] = (1/d_nn) * sum_j S[m][j] * (A0[nn][j]*cvec[j])
// CTA tile M=128(c) N=128(hw) K=512(j), BK=64.
__global__ __launch_bounds__(256, 2) void recon_mma(float* __restrict__ out) {
    extern __shared__ char smem[];
    uint32_t sb = smem_u32(smem);
    float* red = (float*)(smem + OFF_DS);
    float* cs  = (float*)(smem + OFF_CV);
    int tid = threadIdx.x, lane = tid & 31, w = tid >> 5;
    int n = blockIdx.z, hw0 = blockIdx.x * 128, c0 = blockIdx.y * 128;
    int wm = (w & 3) * 32, wn = (w >> 2) * 64;

    if (tid < 128) red[tid] = 0.0f;
    cs[tid] = g_cvec[tid];
    cs[256 + tid] = g_cvec[256 + tid];

    float acc[2][8][4];
#pragma unroll
    for (int a = 0; a < 2; ++a)
#pragma unroll
        for (int b = 0; b < 8; ++b)
#pragma unroll
            for (int c = 0; c < 4; ++c) acc[a][b][c] = 0.0f;

    int crow = tid >> 1, chalf = tid & 1;
    const uint4* aH = (const uint4*)(g_Shc + ((size_t)n * CD + c0 + crow) * KA);
    const uint4* aL = (const uint4*)(g_Slc + ((size_t)n * CD + c0 + crow) * KA);
    const float* arow = g_A0 + ((size_t)(n * HW + hw0 + crow)) * KA;
    __syncthreads();

    for (int ch = 0; ch < 8; ++ch) {
        int k0 = ch * 64;
        // A tile (S hi/lo straight copy)
#pragma unroll
        for (int q = 0; q < 4; ++q) {
            int unit = chalf * 4 + q;
            uint32_t off = swz((uint32_t)(crow * 128 + unit * 16));
            int gi = ch * 8 + unit;
            *(uint4*)(smem + OFF_AH + off) = aH[gi];
            *(uint4*)(smem + OFF_AL + off) = aL[gi];
        }
        // B tile: A0*c -> hi/lo bf16 + row-sum d
        {
            float dp = 0.0f;
#pragma unroll
            for (int qq = 0; qq < 4; ++qq) {
                int jb = k0 + chalf * 32 + qq * 8;
                float4 v0 = *(const float4*)(arow + jb);
                float4 v1 = *(const float4*)(arow + jb + 4);
                v0.x *= cs[jb+0]; v0.y *= cs[jb+1]; v0.z *= cs[jb+2]; v0.w *= cs[jb+3];
                v1.x *= cs[jb+4]; v1.y *= cs[jb+5]; v1.z *= cs[jb+6]; v1.w *= cs[jb+7];
                dp += v0.x + v0.y + v0.z + v0.w + v1.x + v1.y + v1.z + v1.w;
                __nv_bfloat16 h[8], l[8];
                split_bf(v0.x, h[0], l[0]); split_bf(v0.y, h[1], l[1]);
                split_bf(v0.z, h[2], l[2]); split_bf(v0.w, h[3], l[3]);
                split_bf(v1.x, h[4], l[4]); split_bf(v1.y, h[5], l[5]);
                split_bf(v1.z, h[6], l[6]); split_bf(v1.w, h[7], l[7]);
                uint32_t off = swz((uint32_t)(crow * 128 + (chalf * 4 + qq) * 16));
                *(uint4*)(smem + OFF_BH + off) =
                    make_uint4(pack_bf2(h[0],h[1]), pack_bf2(h[2],h[3]),
                               pack_bf2(h[4],h[5]), pack_bf2(h[6],h[7]));
                *(uint4*)(smem + OFF_BL + off) =
                    make_uint4(pack_bf2(l[0],l[1]), pack_bf2(l[2],l[3]),
                               pack_bf2(l[4],l[5]), pack_bf2(l[6],l[7]));
            }
            atomicAdd(&red[crow], dp);
        }
        __syncthreads();
#pragma unroll
        for (int s = 0; s < 4; ++s) {
            uint32_t ah[2][4], al[2][4];
#pragma unroll
            for (int mt = 0; mt < 2; ++mt) {
                ldm4(afrag_addr(sb + OFF_AH, wm + mt * 16, s, lane), ah[mt]);
                ldm4(afrag_addr(sb + OFF_AL, wm + mt * 16, s, lane), al[mt]);
            }
#pragma unroll
            for (int ng = 0; ng < 4; ++ng) {
                uint32_t bh[4], bl[4];
                ldm4(bfrag_addr(sb + OFF_BH, wn + ng * 16, s, lane), bh);
                ldm4(bfrag_addr(sb + OFF_BL, wn + ng * 16, s, lane), bl);
#pragma unroll
                for (int mt = 0; mt < 2; ++mt) {
                    mma16816(acc[mt][2*ng],   ah[mt], bh[0], bh[1]);
                    mma16816(acc[mt][2*ng],   ah[mt], bl[0], bl[1]);
                    mma16816(acc[mt][2*ng],   al[mt], bh[0], bh[1]);
                    mma16816(acc[mt][2*ng+1], ah[mt], bh[2], bh[3]);
                    mma16816(acc[mt][2*ng+1], ah[mt], bl[2], bl[3]);
                    mma16816(acc[mt][2*ng+1], al[mt], bh[2], bh[3]);
                }
            }
        }
        __syncthreads();
    }

    if (tid < 128) red[tid] = 1.0f / fmaxf(red[tid], 1e-30f);
    __syncthreads();

#pragma unroll
    for (int mt = 0; mt < 2; ++mt) {
        int c = c0 + wm + mt * 16 + (lane >> 2);
        int nl = wn + (lane & 3) * 2;
        float* o0 = out + ((size_t)n * CD + c) * HW + hw0 + nl;
        float* o1 = out + ((size_t)n * CD + c + 8) * HW + hw0 + nl;
#pragma unroll
        for (int nt = 0; nt < 8; ++nt) {
            float rx = red[nl + nt * 8], ry = red[nl + nt * 8 + 1];
            *(float2*)(o0 + nt * 8) = make_float2(acc[mt][nt][0] * rx, acc[mt][nt][1] * ry);
            *(float2*)(o1 + nt * 8) = make_float2(acc[mt][nt][2] * rx, acc[mt][nt][3] * ry);
        }
    }
}

// ----------------------------------------------------------------
extern "C" void kernel_launch(void* const* d_in, const int* in_sizes, int n_in,
                              void* d_out, int out_size) {
    const float* x = (const float*)d_in[0];
    const int* idx = (const int*)d_in[1];
    float* out = (float*)d_out;

    cudaFuncSetAttribute(score_mma, cudaFuncAttributeMaxDynamicSharedMemorySize, TC_SMEM);
    cudaFuncSetAttribute(recon_mma, cudaFuncAttributeMaxDynamicSharedMemorySize, TC_SMEM);

    zero_colsum_kernel<<<1, KA>>>();
    norm_kernel<<<ROWS / 256, 256>>>(x);
    xt_kernel<<<dim3(HW / 32, CD / 32, NB), dim3(32, 8)>>>(x);
    gather_cj<<<(NB * CD * KA) / 256, 256>>>(x, idx);
    gather_jc<<<(NB * KA * CD) / 256, 256>>>(x, idx);

    score_mma<<<dim3(HW / 128, KA / 128, NB), 256, TC_SMEM>>>();

    colsum0_kernel<<<ROWS / 128, 256>>>();
    recip_kernel<<<1, KA>>>();                       // c1
    for (int it = 0; it < 3; ++it) {
        sk_pass<<<ROWS / 128, 256>>>();
        recip_kernel<<<1, KA>>>();                   // c2, c3, c4
    }
    recon_mma<<<dim3(HW / 128, CD / 128, NB), 256, TC_SMEM>>>(out);
}